// round 12
// baseline (speedup 1.0000x reference)
#include <cuda_runtime.h>

// Problem constants
#define NB    8
#define NP    2048
#define BN    (NB * NP)
#define ITERS 50
#define PHASES (2 * ITERS)

// upd kernel shape: 256 blocks x 512 threads; 64 rows/block (2 rows/lane),
// 16 warps each owning a 128-j chunk.
#define UWARP 16
#define UJCH  (NP / UWARP)       // 128
#define UTPB  (32 * UWARP)       // 512
#define UGRID (BN / 64)          // 256

// dist kernel shape (runs once): 512 blocks x 256 threads, 32 rows/block
#define DWARP 8
#define DJCH  (NP / DWARP)       // 256
#define DTPB  (32 * DWARP)       // 256

// eps = 0.005
#define SF      288.5390081777927f    // 1/(eps*ln2)
#define TWOSF   577.0780163555854f    // 2/(eps*ln2)
#define EPSLN2  0.0034657359027997264f
#define LOG2NF  11.0f

typedef unsigned long long ULL;

// Global SoA state. h = s*(pot - |p|^2), s = 1/(eps ln2). Coords immutable.
__device__ float g_x1[BN], g_y1[BN], g_z1[BN], g_h1[BN], g_sq1[BN];
__device__ float g_x2[BN], g_y2[BN], g_z2[BN], g_h2[BN], g_sq2[BN];
__device__ float g_part[BN / 32];

// ---------------- helpers ----------------
__device__ __forceinline__ float ex2f(float x) {
    float r; asm("ex2.approx.ftz.f32 %0, %1;" : "=f"(r) : "f"(x)); return r;
}
__device__ __forceinline__ float lg2f(float x) {
    float r; asm("lg2.approx.ftz.f32 %0, %1;" : "=f"(r) : "f"(x)); return r;
}
__device__ __forceinline__ ULL pack2(float lo, float hi) {
    ULL r; asm("mov.b64 %0, {%1, %2};" : "=l"(r) : "f"(lo), "f"(hi)); return r;
}
__device__ __forceinline__ void unpack2(ULL v, float& lo, float& hi) {
    asm("mov.b64 {%0, %1}, %2;" : "=f"(lo), "=f"(hi) : "l"(v));
}
__device__ __forceinline__ ULL fma2(ULL a, ULL b, ULL c) {
    ULL r; asm("fma.rn.f32x2 %0, %1, %2, %3;" : "=l"(r) : "l"(a), "l"(b), "l"(c)); return r;
}
__device__ __forceinline__ ULL add2(ULL a, ULL b) {
    ULL r; asm("add.rn.f32x2 %0, %1, %2;" : "=l"(r) : "l"(a), "l"(b)); return r;
}
// two scalar ex2 -> one packed pair (pack mov expected to be register-aliased)
__device__ __forceinline__ ULL ex2pair(float a, float b) {
    return pack2(ex2f(a), ex2f(b));
}
// 16B shared load -> two packed j-pairs (SoA)
__device__ __forceinline__ void lds4(const float* sp, ULL& a, ULL& b) {
    unsigned addr = (unsigned)__cvta_generic_to_shared(sp);
    asm volatile("ld.shared.v2.b64 {%0, %1}, [%2];" : "=l"(a), "=l"(b) : "r"(addr));
}

// ---------------------------------------------------------------------------
__global__ void init_k(const float* __restrict__ pc1, const float* __restrict__ pc2) {
    int idx = blockIdx.x * blockDim.x + threadIdx.x;
    if (idx >= BN) return;

    float x = pc1[3 * idx + 0], y = pc1[3 * idx + 1], z = pc1[3 * idx + 2];
    float sq = x * x + y * y + z * z;
    g_x1[idx] = x; g_y1[idx] = y; g_z1[idx] = z; g_sq1[idx] = sq; g_h1[idx] = -SF * sq;

    x = pc2[3 * idx + 0]; y = pc2[3 * idx + 1]; z = pc2[3 * idx + 2];
    sq = x * x + y * y + z * z;
    g_x2[idx] = x; g_y2[idx] = y; g_z2[idx] = z; g_sq2[idx] = sq; g_h2[idx] = -SF * sq;
}

// ---------------------------------------------------------------------------
// Half-step, 2 rows per lane, packed f32x2 math AND packed accumulation.
// Lane owns rows rA = row0+lane, rB = rA+32; warp w owns j-chunk [w*128 ..).
// Fast fixed-reference LSE (M0 = -h_old - log2N) + whole-warp online-max
// rescue on over/underflow. 16-warp log-domain merge; rows written by tid<64.
// ---------------------------------------------------------------------------
__global__ void __launch_bounds__(UTPB, 2) upd_k(int dir) {
    const float* __restrict__ jx = dir ? g_x1 : g_x2;
    const float* __restrict__ jy = dir ? g_y1 : g_y2;
    const float* __restrict__ jz = dir ? g_z1 : g_z2;
    const float* __restrict__ jh = dir ? g_h1 : g_h2;
    const float* __restrict__ rx = dir ? g_x2 : g_x1;
    const float* __restrict__ ry = dir ? g_y2 : g_y1;
    const float* __restrict__ rz = dir ? g_z2 : g_z1;
    float*       __restrict__ rh = dir ? g_h2 : g_h1;

    __shared__ __align__(16) float sx[NP], sy[NP], sz[NP], shh[NP];   // 32 KB
    __shared__ float msh[UWARP][64], ssh[UWARP][64];                  // 8 KB

    const int tid  = threadIdx.x;
    const int lane = tid & 31;
    const int w    = tid >> 5;
    const int blk  = blockIdx.x;
    const int b    = blk >> 5;                 // 32 blocks per batch
    const int base = b * NP;
    const int row0 = base + ((blk & 31) << 6); // 64 rows per block
    const int o4   = (w << 5) + lane;          // float4 idx of warp's chunk elt

    // Per-warp staging of own 128-j chunk (1 float4 per lane per array)
    ((float4*)sx)[o4] = __ldg((const float4*)(jx + base) + o4);
    ((float4*)sy)[o4] = __ldg((const float4*)(jy + base) + o4);
    ((float4*)sz)[o4] = __ldg((const float4*)(jz + base) + o4);
    ((float4*)shh)[o4] = __ldg((const float4*)(jh + base) + o4);

    // Row-pair constants
    const int rA = row0 + lane, rB = rA + 32;
    float pxA = TWOSF * __ldg(rx + rA), pxB = TWOSF * __ldg(rx + rB);
    float pyA = TWOSF * __ldg(ry + rA), pyB = TWOSF * __ldg(ry + rB);
    float pzA = TWOSF * __ldg(rz + rA), pzB = TWOSF * __ldg(rz + rB);
    float hwA = __ldg(rh + rA) + LOG2NF;       // -M0 for row A
    float hwB = __ldg(rh + rB) + LOG2NF;
    __syncwarp();

    const float* qx = sx  + w * UJCH;
    const float* qy = sy  + w * UJCH;
    const float* qz = sz  + w * UJCH;
    const float* qh = shh + w * UJCH;

    ULL pxA2 = pack2(pxA, pxA), pyA2 = pack2(pyA, pyA), pzA2 = pack2(pzA, pzA);
    ULL pxB2 = pack2(pxB, pxB), pyB2 = pack2(pyB, pyB), pzB2 = pack2(pzB, pzB);
    ULL hwA2 = pack2(hwA, hwA), hwB2 = pack2(hwB, hwB);

    // packed accumulators: {A-row pair01, A-row pair23, B-row pair01, B-row pair23}
    ULL accA0 = 0ULL, accA1 = 0ULL, accB0 = 0ULL, accB1 = 0ULL;

    #pragma unroll 2
    for (int j = 0; j < UJCH; j += 4) {
        ULL x01, x23, y01, y23, z01, z23, h01, h23;
        lds4(qx + j, x01, x23);
        lds4(qy + j, y01, y23);
        lds4(qz + j, z01, z23);
        lds4(qh + j, h01, h23);

        ULL AA01 = fma2(pxA2, x01, fma2(pyA2, y01, fma2(pzA2, z01, add2(h01, hwA2))));
        ULL AA23 = fma2(pxA2, x23, fma2(pyA2, y23, fma2(pzA2, z23, add2(h23, hwA2))));
        ULL AB01 = fma2(pxB2, x01, fma2(pyB2, y01, fma2(pzB2, z01, add2(h01, hwB2))));
        ULL AB23 = fma2(pxB2, x23, fma2(pyB2, y23, fma2(pzB2, z23, add2(h23, hwB2))));

        float a0, a1, a2, a3;
        unpack2(AA01, a0, a1);
        unpack2(AA23, a2, a3);
        accA0 = add2(accA0, ex2pair(a0, a1));
        accA1 = add2(accA1, ex2pair(a2, a3));
        unpack2(AB01, a0, a1);
        unpack2(AB23, a2, a3);
        accB0 = add2(accB0, ex2pair(a0, a1));
        accB1 = add2(accB1, ex2pair(a2, a3));
    }

    float uA0, uA1, uA2, uA3, uB0, uB1, uB2, uB3;
    unpack2(accA0, uA0, uA1);
    unpack2(accA1, uA2, uA3);
    unpack2(accB0, uB0, uB1);
    unpack2(accB1, uB2, uB3);
    float SA = (uA0 + uA1) + (uA2 + uA3);
    float SB = (uB0 + uB1) + (uB2 + uB3);
    float mA = -hwA, sAo = SA, mB = -hwB, sBo = SB;

    // Rescue: any lane over/underflowed in either row -> exact online-max redo
    bool ok = (SA > 0.0f) && (SA <= 3.3e38f) && (SB > 0.0f) && (SB <= 3.3e38f);
    if (__ballot_sync(0xffffffffu, !ok)) {
        float ma = -1e30f, sa = 0.f, mb = -1e30f, sb = 0.f;
        for (int j = 0; j < UJCH; j++) {
            float xx = qx[j], yy = qy[j], zz = qz[j], hh = qh[j];
            float Aa = fmaf(pxA, xx, fmaf(pyA, yy, fmaf(pzA, zz, hh)));
            float Ab = fmaf(pxB, xx, fmaf(pyB, yy, fmaf(pzB, zz, hh)));
            float na = fmaxf(Aa, ma), nb = fmaxf(Ab, mb);
            sa = sa * ex2f(ma - na) + ex2f(Aa - na);
            sb = sb * ex2f(mb - nb) + ex2f(Ab - nb);
            ma = na; mb = nb;
        }
        mA = ma; sAo = sa; mB = mb; sBo = sb;
    }

    msh[w][lane]      = mA;
    ssh[w][lane]      = sAo;
    msh[w][lane + 32] = mB;
    ssh[w][lane + 32] = sBo;
    __syncthreads();

    if (tid < 64) {
        float M = msh[0][tid];
        #pragma unroll
        for (int k = 1; k < UWARP; k++) M = fmaxf(M, msh[k][tid]);
        float S = 0.f;
        #pragma unroll
        for (int k = 0; k < UWARP; k++) S += ssh[k][tid] * ex2f(msh[k][tid] - M);
        rh[row0 + tid] = -LOG2NF - M - lg2f(S);
    }
}

// ---------------------------------------------------------------------------
// dist_i = N * sum_j exp2(h1_i + A_j) * C_ij ; C = sq1 + sq2 - (A - h_j)*eps*ln2
// Runs once; 8-warp j-split, per-warp SoA staging.
// ---------------------------------------------------------------------------
__global__ void __launch_bounds__(DTPB, 4) dist_k() {
    __shared__ __align__(16) float sx[NP], sy[NP], sz[NP], shh[NP], ssq[NP];
    __shared__ float ssh[DWARP][32];

    const int tid  = threadIdx.x;
    const int lane = tid & 31;
    const int w    = tid >> 5;
    const int blk  = blockIdx.x;
    const int b    = blk >> 6;
    const int base = b * NP;
    const int gi   = base + ((blk & 63) << 5) + lane;

    #pragma unroll
    for (int k = 0; k < 2; k++) {
        int o4 = (w * DJCH >> 2) + lane + 32 * k;
        ((float4*)sx)[o4]  = __ldg((const float4*)(g_x2 + base) + o4);
        ((float4*)sy)[o4]  = __ldg((const float4*)(g_y2 + base) + o4);
        ((float4*)sz)[o4]  = __ldg((const float4*)(g_z2 + base) + o4);
        ((float4*)shh)[o4] = __ldg((const float4*)(g_h2 + base) + o4);
        ((float4*)ssq)[o4] = __ldg((const float4*)(g_sq2 + base) + o4);
    }

    float px = TWOSF * __ldg(g_x1 + gi);
    float py = TWOSF * __ldg(g_y1 + gi);
    float pz = TWOSF * __ldg(g_z1 + gi);
    float sq1 = __ldg(g_sq1 + gi);
    float tf  = __ldg(g_h1 + gi);
    __syncwarp();

    const float* qx = sx  + w * DJCH;
    const float* qy = sy  + w * DJCH;
    const float* qz = sz  + w * DJCH;
    const float* qh = shh + w * DJCH;
    const float* qs = ssq + w * DJCH;

    float a0 = 0.f, a1 = 0.f, a2 = 0.f, a3 = 0.f;
    #pragma unroll 1
    for (int j = 0; j < DJCH; j += 4) {
        #pragma unroll
        for (int k = 0; k < 4; k++) {
            float hj = qh[j + k];
            float A  = fmaf(px, qx[j + k], fmaf(py, qy[j + k], fmaf(pz, qz[j + k], hj)));
            float e  = ex2f(tf + A);
            float C  = sq1 + qs[j + k] - (A - hj) * EPSLN2;
            float pc = e * C;
            if      (k == 0) a0 += pc;
            else if (k == 1) a1 += pc;
            else if (k == 2) a2 += pc;
            else             a3 += pc;
        }
    }
    ssh[w][lane] = (a0 + a1) + (a2 + a3);
    __syncthreads();

    if (w == 0) {
        float S = ssh[0][lane];
        #pragma unroll
        for (int k = 1; k < DWARP; k++) S += ssh[k][lane];
        float v = sqrtf((float)NP * S + 1e-12f);
        #pragma unroll
        for (int o = 16; o; o >>= 1) v += __shfl_xor_sync(0xffffffffu, v, o);
        if (lane == 0) g_part[blk] = v;
    }
}

// ---------------------------------------------------------------------------
__global__ void finish_k(float* __restrict__ out) {
    __shared__ float sh[BN / 32];
    int t = threadIdx.x;
    sh[t] = g_part[t];
    __syncthreads();
    for (int s = (BN / 32) / 2; s > 0; s >>= 1) {
        if (t < s) sh[t] += sh[t + s];
        __syncthreads();
    }
    if (t == 0) out[0] = sh[0] * (1.0f / (float)BN);
}

// ---------------------------------------------------------------------------
extern "C" void kernel_launch(void* const* d_in, const int* in_sizes, int n_in,
                              void* d_out, int out_size) {
    const float* pc1 = (const float*)d_in[0];
    const float* pc2 = (const float*)d_in[1];
    float* out = (float*)d_out;

    init_k<<<(BN + 255) / 256, 256>>>(pc1, pc2);

    for (int p = 0; p < PHASES; p++)
        upd_k<<<UGRID, UTPB>>>(p & 1);

    dist_k<<<BN / 32, DTPB>>>();
    finish_k<<<1, BN / 32>>>(out);

    (void)in_sizes; (void)n_in; (void)out_size;
}